// round 10
// baseline (speedup 1.0000x reference)
#include <cuda_runtime.h>
#include <math.h>

#define BB 8
#define NN 8192
#define HH 32
#define WW 32
#define DD 256
#define HW (HH * WW)                 // 1024
#define ZQ_SIZE (BB * DD * HH * WW)  // 2097152
#define NPOS (BB * HH * WW)          // 8192
#define NGRP 256                     // (b,h) groups
#define NCTA 592                     // 4 * 148 SMs: exactly one wave at occ 4
#define KLW 5e-4f
#define LOG_N 9.010913347279288f     // log(8192)

// cross-CTA scratch (device globals; no allocation). 4 slots per group.
__device__ float        g_pm1[NGRP][4][32];
__device__ int          g_pa1[NGRP][4][32];
__device__ float        g_pS [NGRP][4][32];
__device__ float        g_pT [NGRP][4][32];
__device__ float        g_kl_partial[NGRP];
__device__ unsigned int g_cnt[NGRP];           // per-group arrivals, self-reset
__device__ unsigned int g_done = 0;            // group completions, self-reset

// row partition: rs(c) = floor(c * 131072 / 37); rs(592) = 2^21 exactly.
__device__ __forceinline__ int row_start(int c) {
    return (int)(((long long)c * 131072) / 37);
}
// inverse: CTA owning row r  (verified: r=3541 -> 0, r=3542 -> 1)
__device__ __forceinline__ int cta_of_row(int r) {
    return (int)((((long long)(r + 1) * 37 + 131071) >> 17) - 1);
}

__global__ void __launch_bounds__(256, 4)
gumbel_fused_kernel(const float* __restrict__ z,
                    const float* __restrict__ Wt,
                    const float* __restrict__ g,
                    float* __restrict__ out)
{
    const int c   = blockIdx.x;      // 0..591
    const int tid = threadIdx.x;     // 0..255
    const int grp = tid & 7;         // w-quad: w = grp*4..+3 (warp = 4 full 128B lines)
    const int np  = tid >> 3;        // n-partition 0..31

    // smem union: stats 16KB (phase 1-2) / gather rows 16.5KB (epilogue)
    __shared__ __align__(16) unsigned char s_buf[32 * 129 * 4];  // 16512B
    float (*s_m1)[32] = (float (*)[32])(s_buf);            // [32][32] 4KB
    int   (*s_a1)[32] = (int   (*)[32])(s_buf + 4096);
    float (*s_S )[32] = (float (*)[32])(s_buf + 8192);
    float (*s_T )[32] = (float (*)[32])(s_buf + 12288);
    float (*s_rows)[129] = (float (*)[129])(s_buf);        // [32][129]
    __shared__ int  s_ind[32];
    __shared__ int  s_last, s_fin;

    const int r0 = row_start(c);
    const int r1 = row_start(c + 1);

    for (int gg = (r0 >> 13); gg <= ((r1 - 1) >> 13); ++gg) {
        const int b   = gg >> 5;
        const int h   = gg & 31;
        const int nlo = max(r0 - (gg << 13), 0);
        const int nhi = min(r1 - (gg << 13), NN);

        // ---- phase 1: streaming stats over rows [nlo, nhi) of group gg ----
        float m1x=-INFINITY, m1y=-INFINITY, m1z=-INFINITY, m1w=-INFINITY;
        int   a1x=0x7fffffff, a1y=0x7fffffff, a1z=0x7fffffff, a1w=0x7fffffff;
        float Sx=0.f, Sy=0.f, Sz=0.f, Sw=0.f;
        float Tx=0.f, Ty=0.f, Tz=0.f, Tw=0.f;

        {
            const long long base =
                (long long)(b * NN + nlo + np) * HW + h * WW + grp * 4;
            const float4* zp = (const float4*)(z + base);
            const float4* gp = (const float4*)(g + base);
            #pragma unroll 4
            for (int n = nlo + np; n < nhi; n += 32, zp += 8192, gp += 8192) {
                const float4 zv = __ldg(zp);
                const float4 gv = __ldg(gp);
                float lg;
                lg = zv.x + gv.x; if (lg > m1x) { m1x = lg; a1x = n; }
                lg = zv.y + gv.y; if (lg > m1y) { m1y = lg; a1y = n; }
                lg = zv.z + gv.z; if (lg > m1z) { m1z = lg; a1z = n; }
                lg = zv.w + gv.w; if (lg > m1w) { m1w = lg; a1w = n; }
                float e;
                e = __expf(zv.x); Sx += e; Tx = fmaf(e, zv.x, Tx);
                e = __expf(zv.y); Sy += e; Ty = fmaf(e, zv.y, Ty);
                e = __expf(zv.z); Sz += e; Tz = fmaf(e, zv.z, Tz);
                e = __expf(zv.w); Sw += e; Tw = fmaf(e, zv.w, Tw);
            }
        }

        const int w0 = grp * 4;
        s_m1[np][w0+0]=m1x; s_m1[np][w0+1]=m1y; s_m1[np][w0+2]=m1z; s_m1[np][w0+3]=m1w;
        s_a1[np][w0+0]=a1x; s_a1[np][w0+1]=a1y; s_a1[np][w0+2]=a1z; s_a1[np][w0+3]=a1w;
        s_S [np][w0+0]=Sx;  s_S [np][w0+1]=Sy;  s_S [np][w0+2]=Sz;  s_S [np][w0+3]=Sw;
        s_T [np][w0+0]=Tx;  s_T [np][w0+1]=Ty;  s_T [np][w0+2]=Tz;  s_T [np][w0+3]=Tw;
        __syncthreads();

        // ---- phase 2: in-CTA combine -> slot partial in global scratch ----
        const int c_first = cta_of_row(gg << 13);
        if (tid < 32) {
            const int w = tid;
            float M1 = s_m1[0][w]; int A1 = s_a1[0][w];
            float SS = s_S[0][w];  float TT = s_T[0][w];
            #pragma unroll 8
            for (int i = 1; i < 32; ++i) {
                const float v = s_m1[i][w]; const int a = s_a1[i][w];
                if (v > M1 || (v == M1 && a < A1)) { M1 = v; A1 = a; }
                SS += s_S[i][w];
                TT += s_T[i][w];
            }
            const int slot = c - c_first;
            g_pm1[gg][slot][w] = M1; g_pa1[gg][slot][w] = A1;
            g_pS [gg][slot][w] = SS; g_pT [gg][slot][w] = TT;
        }
        __syncthreads();

        const int nctr = cta_of_row(((gg + 1) << 13) - 1) - c_first + 1;
        if (tid == 0) {
            __threadfence();
            const unsigned old = atomicAdd(&g_cnt[gg], 1u);
            s_last = (old == (unsigned)(nctr - 1));
        }
        __syncthreads();

        if (s_last) {
            __threadfence();         // acquire peer partials
            // ---- combiner: merge slots (in slot order -> deterministic) ----
            if (tid < 32) {
                const int w = tid;
                float M1 = g_pm1[gg][0][w]; int A1 = g_pa1[gg][0][w];
                float SS = g_pS[gg][0][w]; float TT = g_pT[gg][0][w];
                for (int s = 1; s < nctr; ++s) {
                    const float v = g_pm1[gg][s][w]; const int a = g_pa1[gg][s][w];
                    if (v > M1 || (v == M1 && a < A1)) { M1 = v; A1 = a; }
                    SS += g_pS[gg][s][w];
                    TT += g_pT[gg][s][w];
                }
                float kl = TT / SS - __logf(SS) + LOG_N;

                s_ind[w] = A1;
                out[ZQ_SIZE + 1 + gg * 32 + w] = (float)A1;

                #pragma unroll
                for (int off = 16; off; off >>= 1)
                    kl += __shfl_xor_sync(0xffffffffu, kl, off);
                if (w == 0) {
                    g_kl_partial[gg] = kl;
                    g_cnt[gg] = 0;           // reset for next replay
                }
            }
            __syncthreads();         // stats smem free -> reuse as s_rows

            // ---- epilogue: gather 32 rows x 256 d, transposed z_q write ----
            {
                const int lane = tid & 31;
                const int wr   = tid >> 5;   // 8 warps
                const long long obase = (long long)(b * DD) * HW + h * WW + lane;
                #pragma unroll
                for (int halfd = 0; halfd < 2; ++halfd) {
                    const int d0 = halfd * 128;
                    for (int idx = tid; idx < 32 * 128; idx += 256) {
                        const int r = idx >> 7, d = idx & 127;
                        s_rows[r][d] = __ldg(Wt + s_ind[r] * DD + d0 + d);
                    }
                    __syncthreads();
                    #pragma unroll 8
                    for (int k = 0; k < 16; ++k) {
                        const int dl = wr * 16 + k;      // 8 warps x 16 d = 128
                        out[obase + (long long)(d0 + dl) * HW] = s_rows[lane][dl];
                    }
                    __syncthreads();
                }
            }

            // ---- group completion -> final KL scalar by last group ----
            if (tid == 0) {
                __threadfence();
                const unsigned old = atomicAdd(&g_done, 1u);
                s_fin = (old == NGRP - 1);
            }
            __syncthreads();
            if (s_fin) {
                __threadfence();
                float v = g_kl_partial[tid];             // 256 partials, 1/thread
                #pragma unroll
                for (int off = 16; off; off >>= 1)
                    v += __shfl_xor_sync(0xffffffffu, v, off);
                __shared__ float s_red[8];
                if ((tid & 31) == 0) s_red[tid >> 5] = v;
                __syncthreads();
                if (tid == 0) {
                    float x = 0.f;
                    #pragma unroll
                    for (int j = 0; j < 8; ++j) x += s_red[j];
                    out[ZQ_SIZE] = KLW * (x / (float)NPOS);
                    g_done = 0;              // reset for next replay
                }
            }
            __syncthreads();
        }
    }
}

extern "C" void kernel_launch(void* const* d_in, const int* in_sizes, int n_in,
                              void* d_out, int out_size)
{
    const float* z  = (const float*)d_in[0];
    const float* Wt = (const float*)d_in[1];
    const float* g  = (const float*)d_in[2];
    float* out = (float*)d_out;

    gumbel_fused_kernel<<<NCTA, 256>>>(z, Wt, g, out);
}